// round 7
// baseline (speedup 1.0000x reference)
#include <cuda_runtime.h>
#include <cuda_bf16.h>
#include <math.h>

// ---------------- problem constants ----------------
#define TB      16
#define TN      4096
#define TLD     256
#define TH      8
#define TDH     64
#define TWIN    128
#define TINNER  512      // H*DH
#define TFF     1024
#define TDEPTH  4
#define TSLACK  50
#define TOKENS  (TB*TN)  // 65536
#define NWIN    (TN/TWIN) // 32

// weight-split sizes (bf16, K' = 3K)
#define SZ_QKV  (768*1536)
#define SZ_WOUT (1536*256)
#define SZ_W1   (768*1024)
#define SZ_W2   (3072*256)
#define LAYER_SZ (SZ_QKV + SZ_WOUT + SZ_W1 + SZ_W2)
#define WELEMS_PER_LAYER (256*1536 + 512*256 + 256*1024 + 1024*256)  // 1048576

#define GBM 128
#define GBN 128
#define GBK 64
#define G_STAGES 3
#define G_SMEM ((GBM*GBK + GBK*GBN) * 2 * G_STAGES)   // 3 stages, 98304 bytes

// ---------------- scratch (static device allocations) ----------------
__device__ float g_h[(size_t)TOKENS*TLD];
__device__ float g_qkv[(size_t)TOKENS*3*TINNER];
__device__ __nv_bfloat16 g_ah [(size_t)TOKENS*3072];
__device__ __nv_bfloat16 g_ah2[(size_t)TOKENS*3072];
__device__ __nv_bfloat16 g_bw[(size_t)TDEPTH*LAYER_SZ];
__device__ float g_cos[TN*32];
__device__ float g_sin[TN*32];

// ---------------- helpers ----------------
__device__ __forceinline__ float blockSum256(float v) {
    __shared__ float sred[8];
    __syncthreads();
    #pragma unroll
    for (int o = 16; o > 0; o >>= 1) v += __shfl_down_sync(0xffffffffu, v, o);
    if ((threadIdx.x & 31) == 0) sred[threadIdx.x >> 5] = v;
    __syncthreads();
    if (threadIdx.x == 0) {
        float s = 0.f;
        #pragma unroll
        for (int i = 0; i < 8; i++) s += sred[i];
        sred[0] = s;
    }
    __syncthreads();
    return sred[0];
}

__device__ __forceinline__ void split2(float v, __nv_bfloat16& hi, __nv_bfloat16& lo) {
    hi = __float2bfloat16(v);
    lo = __float2bfloat16(v - __bfloat162float(hi));
}

__device__ __forceinline__ void cpasync16(void* dst, const void* src) {
    unsigned int d = (unsigned int)__cvta_generic_to_shared(dst);
    asm volatile("cp.async.cg.shared.global [%0], [%1], 16;\n" :: "r"(d), "l"(src));
}

__device__ __forceinline__ void ldsm_x4(unsigned int& r0, unsigned int& r1,
                                        unsigned int& r2, unsigned int& r3, unsigned int addr) {
    asm volatile("ldmatrix.sync.aligned.m8n8.x4.shared.b16 {%0,%1,%2,%3}, [%4];\n"
                 : "=r"(r0), "=r"(r1), "=r"(r2), "=r"(r3) : "r"(addr));
}
__device__ __forceinline__ void ldsm_x4t(unsigned int& r0, unsigned int& r1,
                                         unsigned int& r2, unsigned int& r3, unsigned int addr) {
    asm volatile("ldmatrix.sync.aligned.m8n8.x4.trans.shared.b16 {%0,%1,%2,%3}, [%4];\n"
                 : "=r"(r0), "=r"(r1), "=r"(r2), "=r"(r3) : "r"(addr));
}
__device__ __forceinline__ void mma16816(float* c, const unsigned int* a,
                                         unsigned int b0, unsigned int b1) {
    asm volatile("mma.sync.aligned.m16n8k16.row.col.f32.bf16.bf16.f32 "
                 "{%0,%1,%2,%3}, {%4,%5,%6,%7}, {%8,%9}, {%0,%1,%2,%3};\n"
                 : "+f"(c[0]), "+f"(c[1]), "+f"(c[2]), "+f"(c[3])
                 : "r"(a[0]), "r"(a[1]), "r"(a[2]), "r"(a[3]), "r"(b0), "r"(b1));
}

__device__ __forceinline__ void g_load_tile(__nv_bfloat16* As, __nv_bfloat16* Bs,
                                            const __nv_bfloat16* A, const __nv_bfloat16* B,
                                            int tid, int rowBase, int colBase,
                                            int k0, int K3, int N) {
    #pragma unroll
    for (int s = 0; s < 4; s++) {
        int i = s * 256 + tid;
        int r = i >> 3, c = i & 7;
        cpasync16(As + r * GBK + ((c ^ (r & 7)) << 3),
                  A + (size_t)(rowBase + r) * K3 + k0 + c * 8);
    }
    #pragma unroll
    for (int s = 0; s < 4; s++) {
        int i = s * 256 + tid;
        int r = i >> 4, c = i & 15;
        cpasync16(Bs + r * GBN + ((c ^ (r & 7)) << 3),
                  B + (size_t)(k0 + r) * N + colBase + c * 8);
    }
    asm volatile("cp.async.commit_group;\n");
}

// ---------------- small kernels ----------------
__global__ void embed_kernel(const float* __restrict__ x, const float* __restrict__ We,
                             const float* __restrict__ be, const float* __restrict__ pe) {
    int t = blockIdx.x, c = threadIdx.x;
    int n = t & (TN - 1);
    float x0 = x[2 * t], x1 = x[2 * t + 1];
    g_h[(size_t)t * TLD + c] = x0 * We[c] + x1 * We[TLD + c] + be[c] + pe[(size_t)n * TLD + c];
}

__global__ void ln_split_kernel(const float* __restrict__ in,
                                const float* __restrict__ g, const float* __restrict__ b) {
    int t = blockIdx.x, c = threadIdx.x;
    float v = in[(size_t)t * TLD + c];
    float mean = blockSum256(v) * (1.0f / TLD);
    float d = v - mean;
    float var = blockSum256(d * d) * (1.0f / TLD);
    float y = d * rsqrtf(var + 1e-5f) * g[c] + b[c];
    __nv_bfloat16 hi, lo;
    split2(y, hi, lo);
    size_t base = (size_t)t * 768;
    g_ah[base + c]       = hi;
    g_ah[base + 256 + c] = lo;
    g_ah[base + 512 + c] = hi;
}

// split ALL layers' weights in ONE launch (so tgemm is launch #4 for ncu).
__global__ void wsplit_all_kernel(const float* __restrict__ Wqkv, const float* __restrict__ Wout,
                                  const float* __restrict__ W1, const float* __restrict__ W2) {
    long long gidx = (long long)blockIdx.x * 256 + threadIdx.x;
    int l = (int)(gidx >> 20);              // WELEMS_PER_LAYER = 2^20
    int idx = (int)(gidx & (WELEMS_PER_LAYER - 1));

    const float* src;
    __nv_bfloat16* dst = g_bw + (size_t)l * LAYER_SZ;
    int K, N, local;
    if (idx < 256 * 1536) {
        src = Wqkv + (size_t)l * 256 * 1536;
        K = 256; N = 1536; local = idx;
    } else if (idx < 256 * 1536 + 512 * 256) {
        src = Wout + (size_t)l * 512 * 256;
        dst += SZ_QKV;
        K = 512; N = 256; local = idx - 256 * 1536;
    } else if (idx < 256 * 1536 + 512 * 256 + 256 * 1024) {
        src = W1 + (size_t)l * 256 * 1024;
        dst += SZ_QKV + SZ_WOUT;
        K = 256; N = 1024; local = idx - (256 * 1536 + 512 * 256);
    } else {
        src = W2 + (size_t)l * 1024 * 256;
        dst += SZ_QKV + SZ_WOUT + SZ_W1;
        K = 1024; N = 256; local = idx - (256 * 1536 + 512 * 256 + 256 * 1024);
    }
    int k = local / N, n = local - k * N;
    __nv_bfloat16 hi, lo;
    split2(src[local], hi, lo);
    dst[(size_t)k * N + n]           = hi;
    dst[(size_t)(K + k) * N + n]     = hi;
    dst[(size_t)(2 * K + k) * N + n] = lo;
}

__global__ void rope_table_kernel() {
    int idx = blockIdx.x * 256 + threadIdx.x;
    int n = idx >> 5, i = idx & 31;
    double inv = exp(-(double)i * (9.210340371976184 / 32.0));
    double ang = (double)n * inv;
    g_cos[idx] = (float)cos(ang);
    g_sin[idx] = (float)sin(ang);
}

// ---------------- tensor-core GEMM (3-stage pipeline, 1 barrier/tile) --------
__global__ void __launch_bounds__(256) tgemm(const __nv_bfloat16* __restrict__ A,
                                             const __nv_bfloat16* __restrict__ B,
                                             const float* __restrict__ bias,
                                             float* __restrict__ C,
                                             __nv_bfloat16* __restrict__ S,
                                             int K3, int N, int epi) {
    extern __shared__ float dynsmem[];
    __nv_bfloat16* sm = reinterpret_cast<__nv_bfloat16*>(dynsmem);

    const int tid = threadIdx.x;
    const int lane = tid & 31, warp = tid >> 5;
    const int wm = warp >> 1, wn = warp & 1;
    const int rowBase = blockIdx.y * GBM, colBase = blockIdx.x * GBN;
    const int stageElems = GBM * GBK + GBK * GBN;

    float acc[2][8][4];
    #pragma unroll
    for (int a = 0; a < 2; a++)
        #pragma unroll
        for (int b = 0; b < 8; b++)
            #pragma unroll
            for (int c = 0; c < 4; c++) acc[a][b][c] = 0.f;

    const int NK = K3 / GBK;   // always >= 12
    g_load_tile(sm,                 sm + GBM * GBK,              A, B, tid, rowBase, colBase, 0,   K3, N);
    g_load_tile(sm + stageElems,    sm + stageElems + GBM * GBK, A, B, tid, rowBase, colBase, GBK, K3, N);

    const int mat = lane >> 3, lr = lane & 7;
    for (int kt = 0; kt < NK; kt++) {
        if (kt < NK - 1) {
            asm volatile("cp.async.wait_group 1;\n");   // tile kt done (kt+1 may fly)
        } else {
            asm volatile("cp.async.wait_group 0;\n");   // last tile: drain all
        }
        __syncthreads();   // all warps done with stage (kt+2)%3's old contents

        if (kt + 2 < NK) {
            __nv_bfloat16* nx = sm + ((kt + 2) % G_STAGES) * stageElems;
            g_load_tile(nx, nx + GBM * GBK, A, B, tid, rowBase, colBase,
                        (kt + 2) * GBK, K3, N);
        }

        const __nv_bfloat16* As = sm + (kt % G_STAGES) * stageElems;
        const __nv_bfloat16* Bs = As + GBM * GBK;
        unsigned int a_base = (unsigned int)__cvta_generic_to_shared(As);
        unsigned int b_base = (unsigned int)__cvta_generic_to_shared(Bs);

        #pragma unroll
        for (int kk = 0; kk < 4; kk++) {
            unsigned int a[2][4];
            #pragma unroll
            for (int mi = 0; mi < 2; mi++) {
                int r  = wm * 32 + mi * 16 + ((mat & 1) << 3) + lr;
                int ch = kk * 2 + (mat >> 1);
                unsigned int addr = a_base + (unsigned int)(r * GBK + ((ch ^ (r & 7)) << 3)) * 2;
                ldsm_x4(a[mi][0], a[mi][1], a[mi][2], a[mi][3], addr);
            }
            #pragma unroll
            for (int nj = 0; nj < 4; nj++) {
                int ni = wn * 8 + nj * 2 + (mat >> 1);
                int kr = kk * 16 + ((mat & 1) << 3) + lr;
                unsigned int addr = b_base + (unsigned int)(kr * GBN + ((ni ^ (kr & 7)) << 3)) * 2;
                unsigned int b0, b1, b2, b3;
                ldsm_x4t(b0, b1, b2, b3, addr);
                #pragma unroll
                for (int mi = 0; mi < 2; mi++) {
                    mma16816(acc[mi][nj * 2],     a[mi], b0, b1);
                    mma16816(acc[mi][nj * 2 + 1], a[mi], b2, b3);
                }
            }
        }
    }

    const int qr = lane >> 2, qc = (lane & 3) * 2;
    #pragma unroll
    for (int mi = 0; mi < 2; mi++) {
        #pragma unroll
        for (int nt = 0; nt < 8; nt++) {
            int row0 = rowBase + wm * 32 + mi * 16 + qr;
            int col  = colBase + wn * 64 + nt * 8 + qc;
            float* cc = acc[mi][nt];
            #pragma unroll
            for (int half = 0; half < 2; half++) {
                int row = row0 + half * 8;
                #pragma unroll
                for (int j = 0; j < 2; j++) {
                    float v = cc[half * 2 + j];
                    int c2 = col + j;
                    size_t off = (size_t)row * N + c2;
                    if (epi == 0) {
                        C[off] = v;
                    } else if (epi == 1) {
                        C[off] += v;
                    } else if (epi == 2) {
                        v += bias[c2];
                        v = 0.5f * v * (1.0f + erff(v * 0.70710678118654752f));
                        __nv_bfloat16 hi, lo;
                        split2(v, hi, lo);
                        size_t sb = (size_t)row * (3 * (size_t)N);
                        S[sb + c2]         = hi;
                        S[sb + N + c2]     = lo;
                        S[sb + 2 * N + c2] = hi;
                    } else {
                        v += bias[c2];
                        C[off] += v;
                    }
                }
            }
        }
    }
}

// ---------------- local attention (v4: 4-way split dot chain) ----------------
__global__ void __launch_bounds__(256) attn_kernel() {
    extern __shared__ float dynsmem[];
    float* Ks = dynsmem;             // 256 x 64
    float* Vs = dynsmem + 256 * 64;  // 256 x 64
    const int iw = blockIdx.x, hh = blockIdx.y, b = blockIdx.z;
    const int tid = threadIdx.x;
    const int lane = tid & 31, warp = tid >> 5;
    const int p = warp * 16 + (lane >> 1);   // query row 0..127
    const int half = lane & 1;               // dim half

    const int tbase = b * TN + (iw - 1) * TWIN;
    for (int idx = tid; idx < 256 * 64; idx += 256) {
        int jj = idx >> 6, d = idx & 63;
        float kk = 0.f, vv = 0.f;
        if (iw > 0 || jj >= TWIN) {
            size_t tk = (size_t)(tbase + jj);
            int ntok = (int)(tk & (TN - 1));
            const float* kp = g_qkv + tk * (3 * TINNER) + TINNER + hh * 64;
            int i = d & 31;
            float c = g_cos[ntok * 32 + i];
            float s = g_sin[ntok * 32 + i];
            float k1 = kp[i], k2 = kp[i + 32];
            kk = (d < 32) ? (k1 * c - k2 * s) : (k2 * c + k1 * s);
            vv = g_qkv[tk * (3 * TINNER) + 2 * TINNER + hh * 64 + d];
        }
        Ks[idx] = kk;
        Vs[idx] = vv;
    }
    __syncthreads();

    const int t = b * TN + iw * TWIN + p;
    const int ntok = t & (TN - 1);
    const float* qp = g_qkv + (size_t)t * (3 * TINNER) + hh * 64;
    float q[32];
    #pragma unroll
    for (int j = 0; j < 32; j++) {
        float c = g_cos[ntok * 32 + j];
        float s = g_sin[ntok * 32 + j];
        float q1 = qp[j], q2 = qp[j + 32];
        float r = (half == 0) ? (q1 * c - q2 * s) : (q2 * c + q1 * s);
        q[j] = r * 0.125f;
    }

    float m = -1e30f, l = 0.f, acc[32];
    #pragma unroll
    for (int j = 0; j < 32; j++) acc[j] = 0.f;

    const int lo_b = (iw == 0) ? TWIN : p;
    const int hi_b = p + TWIN;
    const int lo_w = (iw == 0) ? TWIN : warp * 16;
    const int hi_w = warp * 16 + 15 + TWIN;

    for (int jj = lo_w; jj <= hi_w; jj++) {
        const float* kr = Ks + jj * 64 + half * 32;
        // 4-way split dot: breaks the 32-FMA serial dependency chain
        float p0 = 0.f, p1 = 0.f, p2 = 0.f, p3 = 0.f;
        #pragma unroll
        for (int j = 0; j < 8; j++) {
            p0 += q[j]      * kr[j];
            p1 += q[j + 8]  * kr[j + 8];
            p2 += q[j + 16] * kr[j + 16];
            p3 += q[j + 24] * kr[j + 24];
        }
        float partial = (p0 + p1) + (p2 + p3);
        float s = partial + __shfl_xor_sync(0xffffffffu, partial, 1);
        if (jj < lo_b || jj > hi_b) s = -1e30f;
        float mn = fmaxf(m, s);
        float corr = expf(m - mn);
        float w = expf(s - mn);
        l = l * corr + w;
        const float* vr = Vs + jj * 64 + half * 32;
        #pragma unroll
        for (int j = 0; j < 32; j++) acc[j] = acc[j] * corr + w * vr[j];
        m = mn;
    }
    float invl = 1.0f / l;
    size_t base = (size_t)t * 1536 + hh * 64 + half * 32;
    #pragma unroll
    for (int j = 0; j < 32; j++) {
        float v = acc[j] * invl;
        __nv_bfloat16 hi, lo;
        split2(v, hi, lo);
        g_ah[base + j]        = hi;
        g_ah[base + 512 + j]  = lo;
        g_ah[base + 1024 + j] = hi;
    }
}

// ---------------- final LN + logits ----------------
__global__ void final_kernel(const float* __restrict__ g, const float* __restrict__ bb,
                             const float* __restrict__ Wl, float* __restrict__ out) {
    int t = blockIdx.x, c = threadIdx.x;
    float v = g_h[(size_t)t * TLD + c];
    float mean = blockSum256(v) * (1.0f / TLD);
    float d = v - mean;
    float var = blockSum256(d * d) * (1.0f / TLD);
    float y = d * rsqrtf(var + 1e-5f) * g[c] + bb[c];
    float s = blockSum256(y * Wl[c]);
    if (c == 0) {
        int n = t & (TN - 1), b = t >> 12;
        if (n >= TSLACK && n < TN - TSLACK)
            out[b * (TN - 2 * TSLACK) + (n - TSLACK)] = s;
    }
}

// ---------------- host orchestration ----------------
extern "C" void kernel_launch(void* const* d_in, const int* in_sizes, int n_in,
                              void* d_out, int out_size) {
    const float* x         = (const float*)d_in[0];
    const float* W_exp     = (const float*)d_in[1];
    const float* b_exp     = (const float*)d_in[2];
    const float* pos_emb   = (const float*)d_in[3];
    const float* ln_attn_g = (const float*)d_in[4];
    const float* ln_attn_b = (const float*)d_in[5];
    const float* Wqkv      = (const float*)d_in[6];
    const float* Wout      = (const float*)d_in[7];
    const float* ln_ff_g   = (const float*)d_in[8];
    const float* ln_ff_b   = (const float*)d_in[9];
    const float* W1        = (const float*)d_in[10];
    const float* b1        = (const float*)d_in[11];
    const float* W2        = (const float*)d_in[12];
    const float* b2        = (const float*)d_in[13];
    const float* ln_f_g    = (const float*)d_in[14];
    const float* ln_f_b    = (const float*)d_in[15];
    const float* W_logits  = (const float*)d_in[16];
    float* out = (float*)d_out;

    void *ph, *pqkv, *pah, *pah2, *pbw;
    cudaGetSymbolAddress(&ph,   g_h);
    cudaGetSymbolAddress(&pqkv, g_qkv);
    cudaGetSymbolAddress(&pah,  g_ah);
    cudaGetSymbolAddress(&pah2, g_ah2);
    cudaGetSymbolAddress(&pbw,  g_bw);
    float* H   = (float*)ph;
    __nv_bfloat16* AH  = (__nv_bfloat16*)pah;
    __nv_bfloat16* AH2 = (__nv_bfloat16*)pah2;
    __nv_bfloat16* BW  = (__nv_bfloat16*)pbw;

    cudaFuncSetAttribute(attn_kernel, cudaFuncAttributeMaxDynamicSharedMemorySize, 131072);
    cudaFuncSetAttribute(tgemm, cudaFuncAttributeMaxDynamicSharedMemorySize, G_SMEM);

    // launch 1: all weight splits; launch 2: embed
    wsplit_all_kernel<<<4 * WELEMS_PER_LAYER / 256, 256>>>(Wqkv, Wout, W1, W2);
    embed_kernel<<<TOKENS, 256>>>(x, W_exp, b_exp, pos_emb);

    for (int l = 0; l < TDEPTH; l++) {
        __nv_bfloat16* wb   = BW + (size_t)l * LAYER_SZ;
        __nv_bfloat16* Bqkv = wb;
        __nv_bfloat16* Bout = wb + SZ_QKV;
        __nv_bfloat16* B1w  = wb + SZ_QKV + SZ_WOUT;
        __nv_bfloat16* B2w  = wb + SZ_QKV + SZ_WOUT + SZ_W1;

        // l=0: launch 3 = ln_split, launch 4 = tgemm QKV  <-- ncu capture slot
        ln_split_kernel<<<TOKENS, 256>>>(H, ln_attn_g + l * TLD, ln_attn_b + l * TLD);
        tgemm<<<dim3((3 * TINNER) / GBN, TOKENS / GBM), 256, G_SMEM>>>(
            AH, Bqkv, (const float*)0, (float*)pqkv, (__nv_bfloat16*)0, 768, 3 * TINNER, 0);
        if (l == 0) rope_table_kernel<<<(TN * 32) / 256, 256>>>();   // before first attn
        attn_kernel<<<dim3(NWIN, TH, TB), 256, 131072>>>();
        tgemm<<<dim3(TLD / GBN, TOKENS / GBM), 256, G_SMEM>>>(
            AH, Bout, (const float*)0, H, (__nv_bfloat16*)0, 1536, TLD, 1);
        ln_split_kernel<<<TOKENS, 256>>>(H, ln_ff_g + l * TLD, ln_ff_b + l * TLD);
        tgemm<<<dim3(TFF / GBN, TOKENS / GBM), 256, G_SMEM>>>(
            AH, B1w, b1 + l * TFF, (float*)0, AH2, 768, TFF, 2);
        tgemm<<<dim3(TLD / GBN, TOKENS / GBM), 256, G_SMEM>>>(
            AH2, B2w, b2 + l * TLD, H, (__nv_bfloat16*)0, 3072, TLD, 3);
    }

    final_kernel<<<TOKENS, 256>>>(ln_f_g, ln_f_b, W_logits, out);
}

// round 8
// speedup vs baseline: 1.1236x; 1.1236x over previous
#include <cuda_runtime.h>
#include <cuda_bf16.h>
#include <math.h>

// ---------------- problem constants ----------------
#define TB      16
#define TN      4096
#define TLD     256
#define TH      8
#define TDH     64
#define TWIN    128
#define TINNER  512      // H*DH
#define TFF     1024
#define TDEPTH  4
#define TSLACK  50
#define TOKENS  (TB*TN)  // 65536
#define NWIN    (TN/TWIN) // 32

// weight-split sizes (bf16, K' = 3K)  -- B side keeps full 3K rows
#define SZ_QKV  (768*1536)
#define SZ_WOUT (1536*256)
#define SZ_W1   (768*1024)
#define SZ_W2   (3072*256)
#define LAYER_SZ (SZ_QKV + SZ_WOUT + SZ_W1 + SZ_W2)
#define WELEMS_PER_LAYER (256*1536 + 512*256 + 256*1024 + 1024*256)  // 1048576

#define GBM 128
#define GBN 128
#define GBK 64
#define G_STAGES 3
#define G_SMEM ((GBM*GBK + GBK*GBN) * 2 * G_STAGES)   // 98304 bytes

// ---------------- scratch (static device allocations) ----------------
__device__ float g_h[(size_t)TOKENS*TLD];
__device__ float g_qkv[(size_t)TOKENS*3*TINNER];
__device__ __nv_bfloat16 g_ah [(size_t)TOKENS*1024];   // A' dedup: [hi|lo] stride<=1024
__device__ __nv_bfloat16 g_ah2[(size_t)TOKENS*2048];   // FF acts:  [hi|lo] stride 2048
__device__ __nv_bfloat16 g_bw[(size_t)TDEPTH*LAYER_SZ];
__device__ float g_cos[TN*32];
__device__ float g_sin[TN*32];

// ---------------- helpers ----------------
__device__ __forceinline__ float blockSum256(float v) {
    __shared__ float sred[8];
    __syncthreads();
    #pragma unroll
    for (int o = 16; o > 0; o >>= 1) v += __shfl_down_sync(0xffffffffu, v, o);
    if ((threadIdx.x & 31) == 0) sred[threadIdx.x >> 5] = v;
    __syncthreads();
    if (threadIdx.x == 0) {
        float s = 0.f;
        #pragma unroll
        for (int i = 0; i < 8; i++) s += sred[i];
        sred[0] = s;
    }
    __syncthreads();
    return sred[0];
}

__device__ __forceinline__ void split2(float v, __nv_bfloat16& hi, __nv_bfloat16& lo) {
    hi = __float2bfloat16(v);
    lo = __float2bfloat16(v - __bfloat162float(hi));
}

__device__ __forceinline__ void cpasync16(void* dst, const void* src) {
    unsigned int d = (unsigned int)__cvta_generic_to_shared(dst);
    asm volatile("cp.async.cg.shared.global [%0], [%1], 16;\n" :: "r"(d), "l"(src));
}

__device__ __forceinline__ void ldsm_x4(unsigned int& r0, unsigned int& r1,
                                        unsigned int& r2, unsigned int& r3, unsigned int addr) {
    asm volatile("ldmatrix.sync.aligned.m8n8.x4.shared.b16 {%0,%1,%2,%3}, [%4];\n"
                 : "=r"(r0), "=r"(r1), "=r"(r2), "=r"(r3) : "r"(addr));
}
__device__ __forceinline__ void ldsm_x4t(unsigned int& r0, unsigned int& r1,
                                         unsigned int& r2, unsigned int& r3, unsigned int addr) {
    asm volatile("ldmatrix.sync.aligned.m8n8.x4.trans.shared.b16 {%0,%1,%2,%3}, [%4];\n"
                 : "=r"(r0), "=r"(r1), "=r"(r2), "=r"(r3) : "r"(addr));
}
__device__ __forceinline__ void mma16816(float* c, const unsigned int* a,
                                         unsigned int b0, unsigned int b1) {
    asm volatile("mma.sync.aligned.m16n8k16.row.col.f32.bf16.bf16.f32 "
                 "{%0,%1,%2,%3}, {%4,%5,%6,%7}, {%8,%9}, {%0,%1,%2,%3};\n"
                 : "+f"(c[0]), "+f"(c[1]), "+f"(c[2]), "+f"(c[3])
                 : "r"(a[0]), "r"(a[1]), "r"(a[2]), "r"(a[3]), "r"(b0), "r"(b1));
}

// A row stride is Kphys (=2/3 of logical K3); logical k>=Kphys folds to hi chunk.
__device__ __forceinline__ void g_load_tile(__nv_bfloat16* As, __nv_bfloat16* Bs,
                                            const __nv_bfloat16* A, const __nv_bfloat16* B,
                                            int tid, int rowBase, int colBase,
                                            int k0, int Kphys, int N) {
    int k0a = (k0 >= Kphys) ? (k0 - Kphys) : k0;
    #pragma unroll
    for (int s = 0; s < 4; s++) {
        int i = s * 256 + tid;
        int r = i >> 3, c = i & 7;
        cpasync16(As + r * GBK + ((c ^ (r & 7)) << 3),
                  A + (size_t)(rowBase + r) * Kphys + k0a + c * 8);
    }
    #pragma unroll
    for (int s = 0; s < 4; s++) {
        int i = s * 256 + tid;
        int r = i >> 4, c = i & 15;
        cpasync16(Bs + r * GBN + ((c ^ (r & 7)) << 3),
                  B + (size_t)(k0 + r) * N + colBase + c * 8);
    }
    asm volatile("cp.async.commit_group;\n");
}

// ---------------- small kernels ----------------
__global__ void embed_kernel(const float* __restrict__ x, const float* __restrict__ We,
                             const float* __restrict__ be, const float* __restrict__ pe) {
    int t = blockIdx.x, c = threadIdx.x;
    int n = t & (TN - 1);
    float x0 = x[2 * t], x1 = x[2 * t + 1];
    g_h[(size_t)t * TLD + c] = x0 * We[c] + x1 * We[TLD + c] + be[c] + pe[(size_t)n * TLD + c];
}

// LN -> split store [hi|lo], token stride 512
__global__ void ln_split_kernel(const float* __restrict__ in,
                                const float* __restrict__ g, const float* __restrict__ b) {
    int t = blockIdx.x, c = threadIdx.x;
    float v = in[(size_t)t * TLD + c];
    float mean = blockSum256(v) * (1.0f / TLD);
    float d = v - mean;
    float var = blockSum256(d * d) * (1.0f / TLD);
    float y = d * rsqrtf(var + 1e-5f) * g[c] + b[c];
    __nv_bfloat16 hi, lo;
    split2(y, hi, lo);
    size_t base = (size_t)t * 512;
    g_ah[base + c]       = hi;
    g_ah[base + 256 + c] = lo;
}

// split ALL layers' weights in ONE launch (B' = [hi;hi;lo], full 3K rows)
__global__ void wsplit_all_kernel(const float* __restrict__ Wqkv, const float* __restrict__ Wout,
                                  const float* __restrict__ W1, const float* __restrict__ W2) {
    long long gidx = (long long)blockIdx.x * 256 + threadIdx.x;
    int l = (int)(gidx >> 20);              // WELEMS_PER_LAYER = 2^20
    int idx = (int)(gidx & (WELEMS_PER_LAYER - 1));

    const float* src;
    __nv_bfloat16* dst = g_bw + (size_t)l * LAYER_SZ;
    int K, N, local;
    if (idx < 256 * 1536) {
        src = Wqkv + (size_t)l * 256 * 1536;
        K = 256; N = 1536; local = idx;
    } else if (idx < 256 * 1536 + 512 * 256) {
        src = Wout + (size_t)l * 512 * 256;
        dst += SZ_QKV;
        K = 512; N = 256; local = idx - 256 * 1536;
    } else if (idx < 256 * 1536 + 512 * 256 + 256 * 1024) {
        src = W1 + (size_t)l * 256 * 1024;
        dst += SZ_QKV + SZ_WOUT;
        K = 256; N = 1024; local = idx - (256 * 1536 + 512 * 256);
    } else {
        src = W2 + (size_t)l * 1024 * 256;
        dst += SZ_QKV + SZ_WOUT + SZ_W1;
        K = 1024; N = 256; local = idx - (256 * 1536 + 512 * 256 + 256 * 1024);
    }
    int k = local / N, n = local - k * N;
    __nv_bfloat16 hi, lo;
    split2(src[local], hi, lo);
    dst[(size_t)k * N + n]           = hi;
    dst[(size_t)(K + k) * N + n]     = hi;
    dst[(size_t)(2 * K + k) * N + n] = lo;
}

__global__ void rope_table_kernel() {
    int idx = blockIdx.x * 256 + threadIdx.x;
    int n = idx >> 5, i = idx & 31;
    double inv = exp(-(double)i * (9.210340371976184 / 32.0));
    double ang = (double)n * inv;
    g_cos[idx] = (float)cos(ang);
    g_sin[idx] = (float)sin(ang);
}

// ---------------- tensor-core GEMM (pipelined fragments) ---------------------
// epi 0: C = acc   epi 1: C += acc   epi 2: bias+GELU split-store S (stride 2N)
// epi 3: bias, C += acc
__global__ void __launch_bounds__(256, 2) tgemm(const __nv_bfloat16* __restrict__ A,
                                                const __nv_bfloat16* __restrict__ B,
                                                const float* __restrict__ bias,
                                                float* __restrict__ C,
                                                __nv_bfloat16* __restrict__ S,
                                                int K3, int Kphys, int N, int epi) {
    extern __shared__ float dynsmem[];
    __nv_bfloat16* sm = reinterpret_cast<__nv_bfloat16*>(dynsmem);

    const int tid = threadIdx.x;
    const int lane = tid & 31, warp = tid >> 5;
    const int wm = warp >> 1, wn = warp & 1;
    const int rowBase = blockIdx.y * GBM, colBase = blockIdx.x * GBN;
    const int stageElems = GBM * GBK + GBK * GBN;

    float acc[2][8][4];
    #pragma unroll
    for (int a = 0; a < 2; a++)
        #pragma unroll
        for (int b = 0; b < 8; b++)
            #pragma unroll
            for (int c = 0; c < 4; c++) acc[a][b][c] = 0.f;

    const int NK = K3 / GBK;
    g_load_tile(sm,              sm + GBM * GBK,              A, B, tid, rowBase, colBase, 0,   Kphys, N);
    g_load_tile(sm + stageElems, sm + stageElems + GBM * GBK, A, B, tid, rowBase, colBase, GBK, Kphys, N);

    const int mat = lane >> 3, lr = lane & 7;
    const int ra0 = wm * 32 + ((mat & 1) << 3) + lr;   // A row for mi=0 (mi=1: +16)
    const int kb0 = ((mat & 1) << 3) + lr;             // B k-row base within kk
    const int nb0 = wn * 8 + (mat >> 1);               // B ni base within nj

    unsigned int aF[2][2][4];   // [buf][mi][frag]
    unsigned int bF[2][4];      // [buf][frag]

    for (int kt = 0; kt < NK; kt++) {
        if (kt < NK - 1) {
            asm volatile("cp.async.wait_group 1;\n");
        } else {
            asm volatile("cp.async.wait_group 0;\n");
        }
        __syncthreads();

        if (kt + 2 < NK) {
            __nv_bfloat16* nx = sm + ((kt + 2) % G_STAGES) * stageElems;
            g_load_tile(nx, nx + GBM * GBK, A, B, tid, rowBase, colBase,
                        (kt + 2) * GBK, Kphys, N);
        }

        const __nv_bfloat16* As = sm + (kt % G_STAGES) * stageElems;
        const __nv_bfloat16* Bs = As + GBM * GBK;
        unsigned int a_base = (unsigned int)__cvta_generic_to_shared(As);
        unsigned int b_base = (unsigned int)__cvta_generic_to_shared(Bs);

        // prologue: A frags for kk=0, B frags for (kk=0,nj=0)
        #pragma unroll
        for (int mi = 0; mi < 2; mi++) {
            int r  = ra0 + mi * 16;
            int ch = (mat >> 1);
            unsigned int addr = a_base + (unsigned int)(r * GBK + ((ch ^ (r & 7)) << 3)) * 2;
            ldsm_x4(aF[0][mi][0], aF[0][mi][1], aF[0][mi][2], aF[0][mi][3], addr);
        }
        {
            int kr = kb0;
            unsigned int addr = b_base + (unsigned int)(kr * GBN + ((nb0 ^ (kr & 7)) << 3)) * 2;
            ldsm_x4t(bF[0][0], bF[0][1], bF[0][2], bF[0][3], addr);
        }

        #pragma unroll
        for (int st = 0; st < 16; st++) {
            const int kk = st >> 2, nj = st & 3;
            // prefetch A fragments for kk+1 at the start of each kk
            if (nj == 0 && kk < 3) {
                #pragma unroll
                for (int mi = 0; mi < 2; mi++) {
                    int r  = ra0 + mi * 16;
                    int ch = (kk + 1) * 2 + (mat >> 1);
                    unsigned int addr = a_base + (unsigned int)(r * GBK + ((ch ^ (r & 7)) << 3)) * 2;
                    ldsm_x4(aF[(kk + 1) & 1][mi][0], aF[(kk + 1) & 1][mi][1],
                            aF[(kk + 1) & 1][mi][2], aF[(kk + 1) & 1][mi][3], addr);
                }
            }
            // prefetch next B fragment
            if (st < 15) {
                const int st2 = st + 1, kk2 = st2 >> 2, nj2 = st2 & 3;
                int ni = nb0 + nj2 * 2;
                int kr = kk2 * 16 + kb0;
                unsigned int addr = b_base + (unsigned int)(kr * GBN + ((ni ^ (kr & 7)) << 3)) * 2;
                ldsm_x4t(bF[st2 & 1][0], bF[st2 & 1][1], bF[st2 & 1][2], bF[st2 & 1][3], addr);
            }
            // consume
            #pragma unroll
            for (int mi = 0; mi < 2; mi++) {
                mma16816(acc[mi][nj * 2],     aF[kk & 1][mi], bF[st & 1][0], bF[st & 1][1]);
                mma16816(acc[mi][nj * 2 + 1], aF[kk & 1][mi], bF[st & 1][2], bF[st & 1][3]);
            }
        }
    }

    const int qr = lane >> 2, qc = (lane & 3) * 2;
    #pragma unroll
    for (int mi = 0; mi < 2; mi++) {
        #pragma unroll
        for (int nt = 0; nt < 8; nt++) {
            int row0 = rowBase + wm * 32 + mi * 16 + qr;
            int col  = colBase + wn * 64 + nt * 8 + qc;
            float* cc = acc[mi][nt];
            #pragma unroll
            for (int half = 0; half < 2; half++) {
                int row = row0 + half * 8;
                #pragma unroll
                for (int j = 0; j < 2; j++) {
                    float v = cc[half * 2 + j];
                    int c2 = col + j;
                    size_t off = (size_t)row * N + c2;
                    if (epi == 0) {
                        C[off] = v;
                    } else if (epi == 1) {
                        C[off] += v;
                    } else if (epi == 2) {
                        v += bias[c2];
                        v = 0.5f * v * (1.0f + erff(v * 0.70710678118654752f));
                        __nv_bfloat16 hi, lo;
                        split2(v, hi, lo);
                        size_t sb = (size_t)row * (2 * (size_t)N);
                        S[sb + c2]     = hi;
                        S[sb + N + c2] = lo;
                    } else {
                        v += bias[c2];
                        C[off] += v;
                    }
                }
            }
        }
    }
}

// ---------------- local attention (2 lanes/query, warp-uniform loop) ---------
__global__ void __launch_bounds__(256) attn_kernel() {
    extern __shared__ float dynsmem[];
    float* Ks = dynsmem;             // 256 x 64
    float* Vs = dynsmem + 256 * 64;  // 256 x 64
    const int iw = blockIdx.x, hh = blockIdx.y, b = blockIdx.z;
    const int tid = threadIdx.x;
    const int lane = tid & 31, warp = tid >> 5;
    const int p = warp * 16 + (lane >> 1);
    const int half = lane & 1;

    const int tbase = b * TN + (iw - 1) * TWIN;
    for (int idx = tid; idx < 256 * 64; idx += 256) {
        int jj = idx >> 6, d = idx & 63;
        float kk = 0.f, vv = 0.f;
        if (iw > 0 || jj >= TWIN) {
            size_t tk = (size_t)(tbase + jj);
            int ntok = (int)(tk & (TN - 1));
            const float* kp = g_qkv + tk * (3 * TINNER) + TINNER + hh * 64;
            int i = d & 31;
            float c = g_cos[ntok * 32 + i];
            float s = g_sin[ntok * 32 + i];
            float k1 = kp[i], k2 = kp[i + 32];
            kk = (d < 32) ? (k1 * c - k2 * s) : (k2 * c + k1 * s);
            vv = g_qkv[tk * (3 * TINNER) + 2 * TINNER + hh * 64 + d];
        }
        Ks[idx] = kk;
        Vs[idx] = vv;
    }
    __syncthreads();

    const int t = b * TN + iw * TWIN + p;
    const int ntok = t & (TN - 1);
    const float* qp = g_qkv + (size_t)t * (3 * TINNER) + hh * 64;
    float q[32];
    #pragma unroll
    for (int j = 0; j < 32; j++) {
        float c = g_cos[ntok * 32 + j];
        float s = g_sin[ntok * 32 + j];
        float q1 = qp[j], q2 = qp[j + 32];
        float r = (half == 0) ? (q1 * c - q2 * s) : (q2 * c + q1 * s);
        q[j] = r * 0.125f;
    }

    float m = -1e30f, l = 0.f, acc[32];
    #pragma unroll
    for (int j = 0; j < 32; j++) acc[j] = 0.f;

    const int lo_b = (iw == 0) ? TWIN : p;
    const int hi_b = p + TWIN;
    const int lo_w = (iw == 0) ? TWIN : warp * 16;
    const int hi_w = warp * 16 + 15 + TWIN;

    for (int jj = lo_w; jj <= hi_w; jj++) {
        const float* kr = Ks + jj * 64 + half * 32;
        float p0 = 0.f, p1 = 0.f, p2 = 0.f, p3 = 0.f;
        #pragma unroll
        for (int j = 0; j < 8; j++) {
            p0 += q[j]      * kr[j];
            p1 += q[j + 8]  * kr[j + 8];
            p2 += q[j + 16] * kr[j + 16];
            p3 += q[j + 24] * kr[j + 24];
        }
        float partial = (p0 + p1) + (p2 + p3);
        float s = partial + __shfl_xor_sync(0xffffffffu, partial, 1);
        if (jj < lo_b || jj > hi_b) s = -1e30f;
        float mn = fmaxf(m, s);
        float corr = expf(m - mn);
        float w = expf(s - mn);
        l = l * corr + w;
        const float* vr = Vs + jj * 64 + half * 32;
        #pragma unroll
        for (int j = 0; j < 32; j++) acc[j] = acc[j] * corr + w * vr[j];
        m = mn;
    }
    float invl = 1.0f / l;
    // split store [hi|lo], token stride 1024
    size_t base = (size_t)t * 1024 + hh * 64 + half * 32;
    #pragma unroll
    for (int j = 0; j < 32; j++) {
        float v = acc[j] * invl;
        __nv_bfloat16 hi, lo;
        split2(v, hi, lo);
        g_ah[base + j]       = hi;
        g_ah[base + 512 + j] = lo;
    }
}

// ---------------- final LN + logits ----------------
__global__ void final_kernel(const float* __restrict__ g, const float* __restrict__ bb,
                             const float* __restrict__ Wl, float* __restrict__ out) {
    int t = blockIdx.x, c = threadIdx.x;
    float v = g_h[(size_t)t * TLD + c];
    float mean = blockSum256(v) * (1.0f / TLD);
    float d = v - mean;
    float var = blockSum256(d * d) * (1.0f / TLD);
    float y = d * rsqrtf(var + 1e-5f) * g[c] + bb[c];
    float s = blockSum256(y * Wl[c]);
    if (c == 0) {
        int n = t & (TN - 1), b = t >> 12;
        if (n >= TSLACK && n < TN - TSLACK)
            out[b * (TN - 2 * TSLACK) + (n - TSLACK)] = s;
    }
}

// ---------------- host orchestration ----------------
extern "C" void kernel_launch(void* const* d_in, const int* in_sizes, int n_in,
                              void* d_out, int out_size) {
    const float* x         = (const float*)d_in[0];
    const float* W_exp     = (const float*)d_in[1];
    const float* b_exp     = (const float*)d_in[2];
    const float* pos_emb   = (const float*)d_in[3];
    const float* ln_attn_g = (const float*)d_in[4];
    const float* ln_attn_b = (const float*)d_in[5];
    const float* Wqkv      = (const float*)d_in[6];
    const float* Wout      = (const float*)d_in[7];
    const float* ln_ff_g   = (const float*)d_in[8];
    const float* ln_ff_b   = (const float*)d_in[9];
    const float* W1        = (const float*)d_in[10];
    const float* b1        = (const float*)d_in[11];
    const float* W2        = (const float*)d_in[12];
    const float* b2        = (const float*)d_in[13];
    const float* ln_f_g    = (const float*)d_in[14];
    const float* ln_f_b    = (const float*)d_in[15];
    const float* W_logits  = (const float*)d_in[16];
    float* out = (float*)d_out;

    void *ph, *pqkv, *pah, *pah2, *pbw;
    cudaGetSymbolAddress(&ph,   g_h);
    cudaGetSymbolAddress(&pqkv, g_qkv);
    cudaGetSymbolAddress(&pah,  g_ah);
    cudaGetSymbolAddress(&pah2, g_ah2);
    cudaGetSymbolAddress(&pbw,  g_bw);
    float* H   = (float*)ph;
    __nv_bfloat16* AH  = (__nv_bfloat16*)pah;
    __nv_bfloat16* AH2 = (__nv_bfloat16*)pah2;
    __nv_bfloat16* BW  = (__nv_bfloat16*)pbw;

    cudaFuncSetAttribute(attn_kernel, cudaFuncAttributeMaxDynamicSharedMemorySize, 131072);
    cudaFuncSetAttribute(tgemm, cudaFuncAttributeMaxDynamicSharedMemorySize, G_SMEM);

    // launch 1: all weight splits; launch 2: embed
    wsplit_all_kernel<<<4 * WELEMS_PER_LAYER / 256, 256>>>(Wqkv, Wout, W1, W2);
    embed_kernel<<<TOKENS, 256>>>(x, W_exp, b_exp, pos_emb);

    for (int l = 0; l < TDEPTH; l++) {
        __nv_bfloat16* wb   = BW + (size_t)l * LAYER_SZ;
        __nv_bfloat16* Bqkv = wb;
        __nv_bfloat16* Bout = wb + SZ_QKV;
        __nv_bfloat16* B1w  = wb + SZ_QKV + SZ_WOUT;
        __nv_bfloat16* B2w  = wb + SZ_QKV + SZ_WOUT + SZ_W1;

        // l=0: launch 3 = ln_split, launch 4 = tgemm QKV  <-- ncu capture slot
        ln_split_kernel<<<TOKENS, 256>>>(H, ln_attn_g + l * TLD, ln_attn_b + l * TLD);
        tgemm<<<dim3((3 * TINNER) / GBN, TOKENS / GBM), 256, G_SMEM>>>(
            AH, Bqkv, (const float*)0, (float*)pqkv, (__nv_bfloat16*)0,
            768, 512, 3 * TINNER, 0);
        if (l == 0) rope_table_kernel<<<(TN * 32) / 256, 256>>>();
        attn_kernel<<<dim3(NWIN, TH, TB), 256, 131072>>>();
        tgemm<<<dim3(TLD / GBN, TOKENS / GBM), 256, G_SMEM>>>(
            AH, Bout, (const float*)0, H, (__nv_bfloat16*)0,
            1536, 1024, TLD, 1);
        ln_split_kernel<<<TOKENS, 256>>>(H, ln_ff_g + l * TLD, ln_ff_b + l * TLD);
        tgemm<<<dim3(TFF / GBN, TOKENS / GBM), 256, G_SMEM>>>(
            AH, B1w, b1 + l * TFF, (float*)0, AH2,
            768, 512, TFF, 2);
        tgemm<<<dim3(TLD / GBN, TOKENS / GBM), 256, G_SMEM>>>(
            AH2, B2w, b2 + l * TLD, H, (__nv_bfloat16*)0,
            3072, 2048, TLD, 3);
    }

    final_kernel<<<TOKENS, 256>>>(ln_f_g, ln_f_b, W_logits, out);
}